// round 1
// baseline (speedup 1.0000x reference)
#include <cuda_runtime.h>
#include <cuda_bf16.h>
#include <cstdint>
#include <math.h>

// Problem constants
#define N_IMG 16
#define CI    64
#define H_IN  224
#define W_IN  224
#define CO    128
#define OH    222
#define OW    222

// Tiling
#define TH 8          // output rows per block
#define TW 64         // output cols per block
#define XROWS (TH + 2)        // 10
#define XCOLS (TW + 2)        // 66
#define XSTRIDE 68            // padded to multiple of 4 for float4 alignment
#define XPLANE (XROWS * XSTRIDE)   // 680 floats per ci
#define XSMEM_FLOATS (CI * XPLANE) // 43520

#define CO_CHUNK 8
#define WCHUNK_FLOATS (CO_CHUNK * CI * 9)  // 4608, layout [ci][kh*3+kw][co_l]
#define CI_STRIDE_W (9 * CO_CHUNK)         // 72 floats per ci in staged weights

#define NTHREADS 256

// packed f32x2 helpers
#define FMA2(d, a, b, c) \
    asm("fma.rn.f32x2 %0, %1, %2, %3;" : "=l"(d) : "l"(a), "l"(b), "l"(c))
#define BCAST2(d, x) \
    asm("mov.b64 %0, {%1, %1};" : "=l"(d) : "r"(__float_as_uint(x)))
#define PACK2(d, lo, hi) \
    asm("mov.b64 %0, {%1, %2};" : "=l"(d) : "r"(__float_as_uint(lo)), "r"(__float_as_uint(hi)))
#define UNPACK2(lo, hi, in) do { \
    unsigned _ulo, _uhi; \
    asm("mov.b64 {%0, %1}, %2;" : "=r"(_ulo), "=r"(_uhi) : "l"(in)); \
    lo = __uint_as_float(_ulo); hi = __uint_as_float(_uhi); \
} while (0)

__global__ __launch_bounds__(NTHREADS, 1)
void conv_min_tanh_kernel(const float* __restrict__ x,
                          const float* __restrict__ wgt,
                          const float* __restrict__ bias,
                          float* __restrict__ out)
{
    extern __shared__ float smem[];
    float* xsm    = smem;                        // 43520 floats
    float* wsm    = xsm + XSMEM_FLOATS;          // 4608 floats
    float* biassm = wsm + WCHUNK_FLOATS;         // 128 floats
    float* minbuf = biassm + 128;                // 512 floats

    const int tid = threadIdx.x;
    const int n   = blockIdx.z;
    const int oh0 = blockIdx.y * TH;
    const int ow0 = blockIdx.x * TW;

    // thread decomposition: pos in [0,128): (r, cg); h = co-half
    const int h   = tid >> 7;          // 0 or 1
    const int pos = tid & 127;
    const int r   = pos >> 4;          // 0..7
    const int c0  = (pos & 15) * 4;    // 0..60

    // ---- stage bias ----
    if (tid < CO) biassm[tid] = bias[tid];

    // ---- stage x tile: [ci][row 0..9][col 0..65], guarded ----
    {
        const int total = CI * XROWS * XCOLS;   // 42240
        for (int i = tid; i < total; i += NTHREADS) {
            int ci  = i / (XROWS * XCOLS);
            int rem = i - ci * (XROWS * XCOLS);
            int row = rem / XCOLS;
            int col = rem - row * XCOLS;
            int ih = oh0 + row;
            int iw = ow0 + col;
            float v = 0.0f;
            if (ih < H_IN && iw < W_IN)
                v = x[(((size_t)n * CI + ci) * H_IN + ih) * W_IN + iw];
            xsm[ci * XPLANE + row * XSTRIDE + col] = v;
        }
    }

    float m0 = INFINITY, m1 = INFINITY, m2 = INFINITY, m3 = INFINITY;

    for (int chunk = 0; chunk < CO / CO_CHUNK; ++chunk) {
        const int cobase = chunk * CO_CHUNK;

        __syncthreads();  // protect wsm from previous chunk's readers (also fences x staging)
        // stage weights for this chunk, coalesced gmem reads:
        // i = co_l*576 + rem  ->  wsm[rem*8 + co_l]
        for (int i = tid; i < WCHUNK_FLOATS; i += NTHREADS) {
            int co_l = i / 576;
            int rem  = i - co_l * 576;
            wsm[rem * CO_CHUNK + co_l] = wgt[(size_t)(cobase + co_l) * 576 + rem];
        }
        __syncthreads();

        // accumulators: 4 pixels x 2 co-pairs, init with bias
        uint64_t accInit0, accInit1;
        {
            const float* bp = biassm + cobase + h * 4;
            PACK2(accInit0, bp[0], bp[1]);
            PACK2(accInit1, bp[2], bp[3]);
        }
        uint64_t a00 = accInit0, a01 = accInit1;
        uint64_t a10 = accInit0, a11 = accInit1;
        uint64_t a20 = accInit0, a21 = accInit1;
        uint64_t a30 = accInit0, a31 = accInit1;

        const float* xci = xsm + r * XSTRIDE + c0;
        const float* wci = wsm + h * 4;

        for (int ci = 0; ci < CI; ++ci) {
            const float* xr = xci;
            const float* wk = wci;
            #pragma unroll
            for (int kh = 0; kh < 3; ++kh) {
                const float4 v4 = *(const float4*)(xr);
                const float2 v2 = *(const float2*)(xr + 4);
                uint64_t xx0, xx1, xx2, xx3, xx4, xx5;
                BCAST2(xx0, v4.x); BCAST2(xx1, v4.y);
                BCAST2(xx2, v4.z); BCAST2(xx3, v4.w);
                BCAST2(xx4, v2.x); BCAST2(xx5, v2.y);

                // kw = 0
                {
                    uint64_t w0 = *(const uint64_t*)(wk + 0);
                    uint64_t w1 = *(const uint64_t*)(wk + 2);
                    FMA2(a00, w0, xx0, a00); FMA2(a01, w1, xx0, a01);
                    FMA2(a10, w0, xx1, a10); FMA2(a11, w1, xx1, a11);
                    FMA2(a20, w0, xx2, a20); FMA2(a21, w1, xx2, a21);
                    FMA2(a30, w0, xx3, a30); FMA2(a31, w1, xx3, a31);
                }
                // kw = 1
                {
                    uint64_t w0 = *(const uint64_t*)(wk + 8);
                    uint64_t w1 = *(const uint64_t*)(wk + 10);
                    FMA2(a00, w0, xx1, a00); FMA2(a01, w1, xx1, a01);
                    FMA2(a10, w0, xx2, a10); FMA2(a11, w1, xx2, a11);
                    FMA2(a20, w0, xx3, a20); FMA2(a21, w1, xx3, a21);
                    FMA2(a30, w0, xx4, a30); FMA2(a31, w1, xx4, a31);
                }
                // kw = 2
                {
                    uint64_t w0 = *(const uint64_t*)(wk + 16);
                    uint64_t w1 = *(const uint64_t*)(wk + 18);
                    FMA2(a00, w0, xx2, a00); FMA2(a01, w1, xx2, a01);
                    FMA2(a10, w0, xx3, a10); FMA2(a11, w1, xx3, a11);
                    FMA2(a20, w0, xx4, a20); FMA2(a21, w1, xx4, a21);
                    FMA2(a30, w0, xx5, a30); FMA2(a31, w1, xx5, a31);
                }
                xr += XSTRIDE;
                wk += 24;
            }
            xci += XPLANE;
            wci += CI_STRIDE_W;
        }

        // fold this chunk's 4 co into per-pixel running min
        {
            float lo, hi, lo2, hi2;
            UNPACK2(lo, hi, a00); UNPACK2(lo2, hi2, a01);
            m0 = fminf(m0, fminf(fminf(lo, hi), fminf(lo2, hi2)));
            UNPACK2(lo, hi, a10); UNPACK2(lo2, hi2, a11);
            m1 = fminf(m1, fminf(fminf(lo, hi), fminf(lo2, hi2)));
            UNPACK2(lo, hi, a20); UNPACK2(lo2, hi2, a21);
            m2 = fminf(m2, fminf(fminf(lo, hi), fminf(lo2, hi2)));
            UNPACK2(lo, hi, a30); UNPACK2(lo2, hi2, a31);
            m3 = fminf(m3, fminf(fminf(lo, hi), fminf(lo2, hi2)));
        }
    }

    // ---- cross-half min combine + tanh(tanh) + store ----
    __syncthreads();
    if (h == 1) {
        minbuf[pos * 4 + 0] = m0;
        minbuf[pos * 4 + 1] = m1;
        minbuf[pos * 4 + 2] = m2;
        minbuf[pos * 4 + 3] = m3;
    }
    __syncthreads();
    if (h == 0) {
        const int oh = oh0 + r;
        if (oh < OH) {
            float v[4] = { fminf(m0, minbuf[pos * 4 + 0]),
                           fminf(m1, minbuf[pos * 4 + 1]),
                           fminf(m2, minbuf[pos * 4 + 2]),
                           fminf(m3, minbuf[pos * 4 + 3]) };
            #pragma unroll
            for (int p = 0; p < 4; ++p) {
                int ow = ow0 + c0 + p;
                if (ow < OW)
                    out[((size_t)n * OH + oh) * OW + ow] = tanhf(tanhf(v[p]));
            }
        }
    }
}

extern "C" void kernel_launch(void* const* d_in, const int* in_sizes, int n_in,
                              void* d_out, int out_size)
{
    const float* x    = (const float*)d_in[0];
    const float* wgt  = (const float*)d_in[1];
    const float* bias = (const float*)d_in[2];
    float* out        = (float*)d_out;

    const int smem_bytes = (XSMEM_FLOATS + WCHUNK_FLOATS + 128 + 512) * (int)sizeof(float);
    cudaFuncSetAttribute(conv_min_tanh_kernel,
                         cudaFuncAttributeMaxDynamicSharedMemorySize, smem_bytes);

    dim3 grid((OW + TW - 1) / TW, (OH + TH - 1) / TH, N_IMG);  // (4, 28, 16)
    conv_min_tanh_kernel<<<grid, NTHREADS, smem_bytes>>>(x, wgt, bias, out);
}

// round 3
// speedup vs baseline: 5.3313x; 5.3313x over previous
#include <cuda_runtime.h>
#include <cuda_bf16.h>
#include <cstdint>
#include <math.h>

// ---------------- problem constants ----------------
#define N_IMG 16
#define CI    64
#define HW    224
#define PLANE (HW*HW)       // 50176
#define CO    128
#define OH    222
#define OW    222
#define KPOS  9
#define KTOT  (CI*KPOS)     // 576

// ---------------- config ----------------
#define THREADS 256
#define NSM 148
#define TILES_TOTAL (N_IMG*OH*2)         // 7104 = 148*48
#define TILES_PER_CTA (TILES_TOTAL/NSM)  // 48

// W smem: [co 128][k 576 pad 584] bf16, row stride 1168B (292 words % 32 = 4: conflict-free)
#define WK_PAD   584
#define W_ROWB   (WK_PAD*2)              // 1168
#define OFF_W    0
#define W_BYTES  (CO*W_ROWB)             // 149504

// S smem: [kh 3][col 132][ci 64 pad 88] bf16, col stride 176B (44 words % 32 = 12: conflict-free)
#define S_CIPAD  88
#define S_COLB   (S_CIPAD*2)             // 176
#define S_KHB    (132*S_COLB)            // 23232
#define OFF_S    W_BYTES                 // 149504
#define S_BYTES  (3*S_KHB)               // 69696

#define OFF_BIAS (OFF_S + S_BYTES)       // 219200 (128 floats)
#define OFF_MIN  (OFF_BIAS + 512)        // 219712 (256 floats)
#define SMEM_TOTAL (OFF_MIN + 1024)      // 220736

// ---------------- PTX helpers ----------------
__device__ __forceinline__ uint32_t smem_u32(const void* p) {
    uint32_t a;
    asm("{ .reg .u64 t; cvta.to.shared.u64 t, %1; cvt.u32.u64 %0, t; }" : "=r"(a) : "l"(p));
    return a;
}

#define LDSM_X4(r, addr) \
    asm volatile("ldmatrix.sync.aligned.m8n8.x4.shared.b16 {%0,%1,%2,%3}, [%4];" \
        : "=r"((r)[0]), "=r"((r)[1]), "=r"((r)[2]), "=r"((r)[3]) : "r"(addr))

__device__ __forceinline__ void mma_bf16(float* d, const uint32_t* a, const uint32_t* b) {
    asm volatile("mma.sync.aligned.m16n8k16.row.col.f32.bf16.bf16.f32 "
        "{%0,%1,%2,%3}, {%4,%5,%6,%7}, {%8,%9}, {%0,%1,%2,%3};"
        : "+f"(d[0]), "+f"(d[1]), "+f"(d[2]), "+f"(d[3])
        : "r"(a[0]), "r"(a[1]), "r"(a[2]), "r"(a[3]), "r"(b[0]), "r"(b[1]));
}

__device__ __forceinline__ uint32_t pack_bf16(float lo, float hi) {
    __nv_bfloat162 t = __floats2bfloat162_rn(lo, hi);
    return *(uint32_t*)&t;
}

// ---------------- kernel ----------------
__global__ __launch_bounds__(THREADS, 1)
void conv_min_tanh_mma(const float* __restrict__ x,
                       const float* __restrict__ wgt,
                       const float* __restrict__ bias,
                       float* __restrict__ out)
{
    extern __shared__ char smem[];
    const uint32_t sb = smem_u32(smem);
    const int tid  = threadIdx.x;
    const int lane = tid & 31;
    const int wid  = tid >> 5;
    const int wm   = wid & 3;   // pixel group (32 pixels)
    const int wn   = wid >> 2;  // co half (64 co)
    float* bias_sm = (float*)(smem + OFF_BIAS);
    float* min_sm  = (float*)(smem + OFF_MIN);

    // ---- stage weights once: W[co][k], k = kp*64 + ci, bf16 ----
    for (int i = tid; i < CO * KTOT; i += THREADS) {
        int co  = i / KTOT;
        int rem = i - co * KTOT;        // ci*9 + kp
        int ci  = rem / KPOS;
        int kp  = rem - ci * KPOS;
        int k   = kp * 64 + ci;
        *(__nv_bfloat16*)(smem + OFF_W + co * W_ROWB + k * 2) = __float2bfloat16(wgt[i]);
    }
    if (tid < CO) bias_sm[tid] = bias[tid];

    // ---- per-thread bias regs for epilogue: co = wn*64 + nt*8 + 2*(lane&3) + {0,1} ----
    float blo[8], bhi[8];
    // (bias_sm written this block; sync before reading)
    __syncthreads();
    #pragma unroll
    for (int nt = 0; nt < 8; ++nt) {
        int c = wn * 64 + nt * 8 + 2 * (lane & 3);
        blo[nt] = bias_sm[c];
        bhi[nt] = bias_sm[c + 1];
    }

    // ldmatrix lane addresses
    // A: S[m = wm*32 + (lane%16) (+kw, +mi*16)][ci = ks*16 + (lane/16)*8]
    const uint32_t aBase = sb + OFF_S + (uint32_t)(wm * 32 + (lane & 15)) * S_COLB
                              + (uint32_t)(lane >> 4) * 16;
    // B: W[co = wn*64 + (lane%8) + ((lane>>4)&1)*8 (+ntp*16)][k + ((lane>>3)&1)*8]
    const uint32_t bBase = sb + OFF_W
        + (uint32_t)(wn * 64 + (lane & 7) + ((lane >> 4) & 1) * 8) * W_ROWB
        + (uint32_t)((lane >> 3) & 1) * 16;

    for (int iter = 0; iter < TILES_PER_CTA; ++iter) {
        const int t   = blockIdx.x * TILES_PER_CTA + iter;
        const int n   = t / (OH * 2);
        const int r2  = t - n * (OH * 2);
        const int oh  = r2 >> 1;
        const int ow0 = (r2 & 1) ? (OW - 128) : 0;   // 0 or 94

        __syncthreads();  // protect S and min_sm from previous tile readers

        // ---- stage S: 120 warp-tasks (kh, ci-octet, col-group) ----
        for (int tk = wid; tk < 120; tk += 8) {
            int kh  = tk / 40;
            int r   = tk - kh * 40;
            int oct = r / 5;
            int cg  = r - oct * 5;
            int col = cg * 32 + lane;
            bool stv = (col < 132);
            bool ldv = stv && (ow0 + col < HW);
            const float* gp = x + ((size_t)n * CI + oct * 8) * PLANE
                                + (size_t)(oh + kh) * HW + (ow0 + col);
            float v[8];
            #pragma unroll
            for (int j = 0; j < 8; ++j) v[j] = ldv ? gp[(size_t)j * PLANE] : 0.0f;
            if (stv) {
                uint32_t pk[4];
                #pragma unroll
                for (int j = 0; j < 4; ++j) pk[j] = pack_bf16(v[2 * j], v[2 * j + 1]);
                uint32_t sa = sb + OFF_S + kh * S_KHB + col * S_COLB + oct * 16;
                asm volatile("st.shared.v4.b32 [%0], {%1,%2,%3,%4};"
                             :: "r"(sa), "r"(pk[0]), "r"(pk[1]), "r"(pk[2]), "r"(pk[3]));
            }
        }
        __syncthreads();

        // ---- MMA: K = 9 kpos x 4 ksteps of 16 ----
        float acc[2][8][4];
        #pragma unroll
        for (int mi = 0; mi < 2; ++mi)
            #pragma unroll
            for (int nt = 0; nt < 8; ++nt)
                #pragma unroll
                for (int q = 0; q < 4; ++q) acc[mi][nt][q] = 0.0f;

        #pragma unroll 1
        for (int kp = 0; kp < KPOS; ++kp) {
            const int kh = kp / 3, kw = kp - 3 * (kp / 3);
            const uint32_t aKp = aBase + kh * S_KHB + kw * S_COLB;
            const uint32_t kB  = (uint32_t)(kp * 64) * 2;
            #pragma unroll
            for (int ks = 0; ks < 4; ++ks) {
                uint32_t a0[4], a1[4];
                LDSM_X4(a0, aKp + ks * 32);
                LDSM_X4(a1, aKp + ks * 32 + 16 * S_COLB);
                uint32_t bf[4][4];
                #pragma unroll
                for (int ntp = 0; ntp < 4; ++ntp)
                    LDSM_X4(bf[ntp], bBase + (uint32_t)ntp * 16 * W_ROWB + kB + ks * 32);
                #pragma unroll
                for (int ntp = 0; ntp < 4; ++ntp) {
                    mma_bf16(acc[0][2 * ntp + 0], a0, &bf[ntp][0]);
                    mma_bf16(acc[0][2 * ntp + 1], a0, &bf[ntp][2]);
                    mma_bf16(acc[1][2 * ntp + 0], a1, &bf[ntp][0]);
                    mma_bf16(acc[1][2 * ntp + 1], a1, &bf[ntp][2]);
                }
            }
        }

        // ---- epilogue: bias + min over co, cross-lane, cross-warp ----
        float v4[4];  // [mi*2 + h], h: 0 = row, 1 = row+8
        #pragma unroll
        for (int mi = 0; mi < 2; ++mi) {
            float r0 = INFINITY, r1 = INFINITY;
            #pragma unroll
            for (int nt = 0; nt < 8; ++nt) {
                r0 = fminf(r0, fminf(acc[mi][nt][0] + blo[nt], acc[mi][nt][1] + bhi[nt]));
                r1 = fminf(r1, fminf(acc[mi][nt][2] + blo[nt], acc[mi][nt][3] + bhi[nt]));
            }
            v4[mi * 2 + 0] = r0;
            v4[mi * 2 + 1] = r1;
        }
        #pragma unroll
        for (int j = 0; j < 4; ++j) {
            v4[j] = fminf(v4[j], __shfl_xor_sync(0xFFFFFFFFu, v4[j], 1));
            v4[j] = fminf(v4[j], __shfl_xor_sync(0xFFFFFFFFu, v4[j], 2));
        }
        if ((lane & 3) == 0) {
            int row = lane >> 2;
            #pragma unroll
            for (int mi = 0; mi < 2; ++mi) {
                min_sm[wn * 128 + wm * 32 + mi * 16 + row]     = v4[mi * 2 + 0];
                min_sm[wn * 128 + wm * 32 + mi * 16 + row + 8] = v4[mi * 2 + 1];
            }
        }
        __syncthreads();
        if (tid < 128) {
            float m = fminf(min_sm[tid], min_sm[tid + 128]);
            out[((size_t)n * OH + oh) * OW + ow0 + tid] = tanhf(tanhf(m));
        }
    }
}

extern "C" void kernel_launch(void* const* d_in, const int* in_sizes, int n_in,
                              void* d_out, int out_size)
{
    const float* x    = (const float*)d_in[0];
    const float* wgt  = (const float*)d_in[1];
    const float* bias = (const float*)d_in[2];
    float* out        = (float*)d_out;

    cudaFuncSetAttribute(conv_min_tanh_mma,
                         cudaFuncAttributeMaxDynamicSharedMemorySize, SMEM_TOTAL);
    conv_min_tanh_mma<<<NSM, THREADS, SMEM_TOTAL>>>(x, wgt, bias, out);
}

// round 4
// speedup vs baseline: 7.4304x; 1.3937x over previous
#include <cuda_runtime.h>
#include <cuda_bf16.h>
#include <cstdint>
#include <math.h>

// ---------------- problem constants ----------------
#define N_IMG 16
#define CI    64
#define HW    224
#define PLANE (HW*HW)       // 50176
#define CO    128
#define OH    222
#define OW    222
#define KPOS  9
#define KTOT  (CI*KPOS)     // 576

// ---------------- config ----------------
#define THREADS 256
#define NSM 148
#define TILES_TOTAL (N_IMG*OH*2)         // 7104 = 148*48
#define TILES_PER_CTA (TILES_TOTAL/NSM)  // 48

// W smem: [co 128][k 576 pad 584] bf16, row stride 1168B (292 words % 32 = 4: conflict-free)
#define WK_PAD   584
#define W_ROWB   (WK_PAD*2)              // 1168
#define OFF_W    0
#define W_BYTES  (CO*W_ROWB)             // 149504

// S smem: ring of 4 planes, plane = [col 132][ci 64 pad 72] bf16
// col stride 144B = 36 words; banks(8 rows, stride 36w) = 4r -> conflict-free LDSM & STS.128
#define S_CIPAD  72
#define S_COLB   (S_CIPAD*2)             // 144
#define S_PLANEB (132*S_COLB)            // 19008
#define OFF_S    W_BYTES                 // 149504
#define S_BYTES  (4*S_PLANEB)            // 76032

#define OFF_BIAS (OFF_S + S_BYTES)       // 225536 (128 floats)
#define OFF_MIN  (OFF_BIAS + 512)        // 226048 (256 floats)
#define SMEM_TOTAL (OFF_MIN + 1024)      // 227072

// ---------------- PTX helpers ----------------
__device__ __forceinline__ uint32_t smem_u32(const void* p) {
    uint32_t a;
    asm("{ .reg .u64 t; cvta.to.shared.u64 t, %1; cvt.u32.u64 %0, t; }" : "=r"(a) : "l"(p));
    return a;
}

#define LDSM_X4(r, addr) \
    asm volatile("ldmatrix.sync.aligned.m8n8.x4.shared.b16 {%0,%1,%2,%3}, [%4];" \
        : "=r"((r)[0]), "=r"((r)[1]), "=r"((r)[2]), "=r"((r)[3]) : "r"(addr))

__device__ __forceinline__ void mma_bf16(float* d, const uint32_t* a, const uint32_t* b) {
    asm volatile("mma.sync.aligned.m16n8k16.row.col.f32.bf16.bf16.f32 "
        "{%0,%1,%2,%3}, {%4,%5,%6,%7}, {%8,%9}, {%0,%1,%2,%3};"
        : "+f"(d[0]), "+f"(d[1]), "+f"(d[2]), "+f"(d[3])
        : "r"(a[0]), "r"(a[1]), "r"(a[2]), "r"(a[3]), "r"(b[0]), "r"(b[1]));
}

__device__ __forceinline__ uint32_t pack_bf16(float lo, float hi) {
    __nv_bfloat162 t = __floats2bfloat162_rn(lo, hi);
    return *(uint32_t*)&t;
}

// ---------------- staging helpers ----------------
// One plane = input row r_in of all 64 ci, cols [ow0, ow0+132).
// 40 tasks: oct(8) x colgroup(5); per warp 5 tasks (tk = wid + 8j).
__device__ __forceinline__ void stage_plane_direct(
    const float* __restrict__ x, int n, int r_in, int ow0,
    uint32_t sb, int wid, int lane)
{
    const uint32_t slotB = sb + OFF_S + (uint32_t)(r_in & 3) * S_PLANEB;
    #pragma unroll
    for (int j = 0; j < 5; ++j) {
        int tk  = wid + 8 * j;
        int oct = tk / 5;
        int cg  = tk - oct * 5;
        int col = cg * 32 + lane;
        bool stv = (col < 132);
        bool ldv = stv && (ow0 + col < HW);
        const float* gp = x + ((size_t)n * CI + oct * 8) * PLANE
                            + (size_t)r_in * HW + (ow0 + col);
        float v[8];
        #pragma unroll
        for (int q = 0; q < 8; ++q) v[q] = ldv ? gp[(size_t)q * PLANE] : 0.0f;
        if (stv) {
            uint32_t pk0 = pack_bf16(v[0], v[1]);
            uint32_t pk1 = pack_bf16(v[2], v[3]);
            uint32_t pk2 = pack_bf16(v[4], v[5]);
            uint32_t pk3 = pack_bf16(v[6], v[7]);
            uint32_t sa = slotB + (uint32_t)col * S_COLB + (uint32_t)oct * 16;
            asm volatile("st.shared.v4.b32 [%0], {%1,%2,%3,%4};"
                         :: "r"(sa), "r"(pk0), "r"(pk1), "r"(pk2), "r"(pk3));
        }
    }
}

// ---------------- kernel ----------------
__global__ __launch_bounds__(THREADS, 1)
void conv_min_tanh_mma2(const float* __restrict__ x,
                        const float* __restrict__ wgt,
                        const float* __restrict__ bias,
                        float* __restrict__ out)
{
    extern __shared__ char smem[];
    const uint32_t sb = smem_u32(smem);
    const int tid  = threadIdx.x;
    const int lane = tid & 31;
    const int wid  = tid >> 5;
    const int wm   = wid & 3;   // pixel group (32 pixels)
    const int wn   = wid >> 2;  // co half (64 co)
    float* bias_sm = (float*)(smem + OFF_BIAS);
    float* min_sm  = (float*)(smem + OFF_MIN);

    // ---- stage weights once: W[co][k], k = kp*64 + ci, bf16 ----
    for (int i = tid; i < CO * KTOT; i += THREADS) {
        int co  = i / KTOT;
        int rem = i - co * KTOT;        // ci*9 + kp
        int ci  = rem / KPOS;
        int kp  = rem - ci * KPOS;
        int k   = kp * 64 + ci;
        *(__nv_bfloat16*)(smem + OFF_W + co * W_ROWB + k * 2) = __float2bfloat16(wgt[i]);
    }
    if (tid < CO) bias_sm[tid] = bias[tid];
    __syncthreads();

    // per-thread bias regs: co = wn*64 + nt*8 + 2*(lane&3) + {0,1}
    float blo[8], bhi[8];
    #pragma unroll
    for (int nt = 0; nt < 8; ++nt) {
        int c = wn * 64 + nt * 8 + 2 * (lane & 3);
        blo[nt] = bias_sm[c];
        bhi[nt] = bias_sm[c + 1];
    }

    // ldmatrix lane address components
    const uint32_t aCol = (uint32_t)(wm * 32 + (lane & 15)) * S_COLB
                        + (uint32_t)(lane >> 4) * 16;
    const uint32_t bBase = sb + OFF_W
        + (uint32_t)(wn * 64 + (lane & 7) + ((lane >> 4) & 1) * 8) * W_ROWB
        + (uint32_t)((lane >> 3) & 1) * 16;

    int prev_strip = -1;

    for (int iter = 0; iter < TILES_PER_CTA; ++iter) {
        const int t     = blockIdx.x * TILES_PER_CTA + iter;
        const int strip = t / OH;              // 0..31 : (n, half)
        const int oh    = t - strip * OH;      // row within strip
        const int n     = strip >> 1;
        const int ow0   = (strip & 1) ? (OW - 128) : 0;

        // ---- strip entry: stage 3 planes fresh ----
        if (strip != prev_strip) {
            // previous iteration ended with __syncthreads(); S slots free
            stage_plane_direct(x, n, oh + 0, ow0, sb, wid, lane);
            stage_plane_direct(x, n, oh + 1, ow0, sb, wid, lane);
            stage_plane_direct(x, n, oh + 2, ow0, sb, wid, lane);
            __syncthreads();
            prev_strip = strip;
        }
        // invariant: planes oh, oh+1, oh+2 in ring slots, visible

        const bool next_same = (iter + 1 < TILES_PER_CTA) && (oh + 1 < OH);

        // ---- prefetch next plane (input row oh+3) into registers ----
        float pf[5][8];
        if (next_same) {
            const int r_in = oh + 3;
            #pragma unroll
            for (int j = 0; j < 5; ++j) {
                int tk  = wid + 8 * j;
                int oct = tk / 5;
                int cg  = tk - oct * 5;
                int col = cg * 32 + lane;
                bool ldv = (col < 132) && (ow0 + col < HW);
                const float* gp = x + ((size_t)n * CI + oct * 8) * PLANE
                                    + (size_t)r_in * HW + (ow0 + col);
                #pragma unroll
                for (int q = 0; q < 8; ++q) pf[j][q] = ldv ? gp[(size_t)q * PLANE] : 0.0f;
            }
        }

        // ---- MMA: K = 9 kpos x 4 ksteps of 16 ----
        float acc[2][8][4];
        #pragma unroll
        for (int mi = 0; mi < 2; ++mi)
            #pragma unroll
            for (int nt = 0; nt < 8; ++nt)
                #pragma unroll
                for (int q = 0; q < 4; ++q) acc[mi][nt][q] = 0.0f;

        #pragma unroll 1
        for (int kp = 0; kp < KPOS; ++kp) {
            const int kh = kp / 3, kw = kp - 3 * (kp / 3);
            const uint32_t aKp = sb + OFF_S + (uint32_t)((oh + kh) & 3) * S_PLANEB
                               + aCol + (uint32_t)kw * S_COLB;
            const uint32_t kB  = (uint32_t)(kp * 64) * 2;
            #pragma unroll
            for (int ks = 0; ks < 4; ++ks) {
                uint32_t a0[4], a1[4];
                LDSM_X4(a0, aKp + ks * 32);
                LDSM_X4(a1, aKp + ks * 32 + 16 * S_COLB);
                uint32_t bf[4][4];
                #pragma unroll
                for (int ntp = 0; ntp < 4; ++ntp)
                    LDSM_X4(bf[ntp], bBase + (uint32_t)ntp * 16 * W_ROWB + kB + ks * 32);
                #pragma unroll
                for (int ntp = 0; ntp < 4; ++ntp) {
                    mma_bf16(acc[0][2 * ntp + 0], a0, &bf[ntp][0]);
                    mma_bf16(acc[0][2 * ntp + 1], a0, &bf[ntp][2]);
                    mma_bf16(acc[1][2 * ntp + 0], a1, &bf[ntp][0]);
                    mma_bf16(acc[1][2 * ntp + 1], a1, &bf[ntp][2]);
                }
            }
        }

        // ---- epilogue: bias + min over co, cross-lane, cross-warp ----
        float v4[4];
        #pragma unroll
        for (int mi = 0; mi < 2; ++mi) {
            float r0 = INFINITY, r1 = INFINITY;
            #pragma unroll
            for (int nt = 0; nt < 8; ++nt) {
                r0 = fminf(r0, fminf(acc[mi][nt][0] + blo[nt], acc[mi][nt][1] + bhi[nt]));
                r1 = fminf(r1, fminf(acc[mi][nt][2] + blo[nt], acc[mi][nt][3] + bhi[nt]));
            }
            v4[mi * 2 + 0] = r0;
            v4[mi * 2 + 1] = r1;
        }
        #pragma unroll
        for (int j = 0; j < 4; ++j) {
            v4[j] = fminf(v4[j], __shfl_xor_sync(0xFFFFFFFFu, v4[j], 1));
            v4[j] = fminf(v4[j], __shfl_xor_sync(0xFFFFFFFFu, v4[j], 2));
        }
        if ((lane & 3) == 0) {
            int row = lane >> 2;
            #pragma unroll
            for (int mi = 0; mi < 2; ++mi) {
                min_sm[wn * 128 + wm * 32 + mi * 16 + row]     = v4[mi * 2 + 0];
                min_sm[wn * 128 + wm * 32 + mi * 16 + row + 8] = v4[mi * 2 + 1];
            }
        }
        __syncthreads();
        if (tid < 128) {
            float m = fminf(min_sm[tid], min_sm[tid + 128]);
            out[((size_t)n * OH + oh) * OW + ow0 + tid] = tanhf(tanhf(m));
        }

        // ---- store prefetched plane into ring slot (oh+3)&3 ----
        // slot (oh+3)&3 == (oh-1)&3: its last readers finished before the sync above.
        if (next_same) {
            const uint32_t slotB = sb + OFF_S + (uint32_t)((oh + 3) & 3) * S_PLANEB;
            #pragma unroll
            for (int j = 0; j < 5; ++j) {
                int tk  = wid + 8 * j;
                int oct = tk / 5;
                int cg  = tk - oct * 5;
                int col = cg * 32 + lane;
                if (col < 132) {
                    uint32_t pk0 = pack_bf16(pf[j][0], pf[j][1]);
                    uint32_t pk1 = pack_bf16(pf[j][2], pf[j][3]);
                    uint32_t pk2 = pack_bf16(pf[j][4], pf[j][5]);
                    uint32_t pk3 = pack_bf16(pf[j][6], pf[j][7]);
                    uint32_t sa = slotB + (uint32_t)col * S_COLB + (uint32_t)oct * 16;
                    asm volatile("st.shared.v4.b32 [%0], {%1,%2,%3,%4};"
                                 :: "r"(sa), "r"(pk0), "r"(pk1), "r"(pk2), "r"(pk3));
                }
            }
        }
        __syncthreads();  // plane visible for next row; min_sm safe for reuse
    }
}

extern "C" void kernel_launch(void* const* d_in, const int* in_sizes, int n_in,
                              void* d_out, int out_size)
{
    const float* x    = (const float*)d_in[0];
    const float* wgt  = (const float*)d_in[1];
    const float* bias = (const float*)d_in[2];
    float* out        = (float*)d_out;

    cudaFuncSetAttribute(conv_min_tanh_mma2,
                         cudaFuncAttributeMaxDynamicSharedMemorySize, SMEM_TOTAL);
    conv_min_tanh_mma2<<<NSM, THREADS, SMEM_TOTAL>>>(x, wgt, bias, out);
}

// round 5
// speedup vs baseline: 7.6953x; 1.0357x over previous
#include <cuda_runtime.h>
#include <cuda_bf16.h>
#include <cstdint>
#include <math.h>

// ---------------- problem constants ----------------
#define N_IMG 16
#define CI    64
#define HW    224
#define PLANE (HW*HW)       // 50176
#define CO    128
#define OH    222
#define OW    222
#define KPOS  9
#define KTOT  (CI*KPOS)     // 576

// ---------------- config ----------------
#define THREADS 512
#define NWARPS  16
#define NSM 148
#define TILES_TOTAL (N_IMG*OH*2)         // 7104 = 148*48
#define TILES_PER_CTA (TILES_TOTAL/NSM)  // 48

// W smem: [co 128][k 576 pad 584] bf16, row stride 1168B (292 words % 32 = 4: conflict-free)
#define WK_PAD   584
#define W_ROWB   (WK_PAD*2)              // 1168
#define OFF_W    0
#define W_BYTES  (CO*W_ROWB)             // 149504

// S smem: ring of 4 planes, plane = [col 132][ci 64 pad 72] bf16
// col stride 144B = 36 words -> conflict-free LDSM & STS.128
#define S_CIPAD  72
#define S_COLB   (S_CIPAD*2)             // 144
#define S_PLANEB (132*S_COLB)            // 19008
#define OFF_S    W_BYTES                 // 149504
#define S_BYTES  (4*S_PLANEB)            // 76032

#define OFF_BIAS (OFF_S + S_BYTES)       // 225536 (128 floats)
#define OFF_MIN  (OFF_BIAS + 512)        // 226048 (512 floats: [px][wn])
#define SMEM_TOTAL (OFF_MIN + 2048)      // 228096

// ---------------- PTX helpers ----------------
__device__ __forceinline__ uint32_t smem_u32(const void* p) {
    uint32_t a;
    asm("{ .reg .u64 t; cvta.to.shared.u64 t, %1; cvt.u32.u64 %0, t; }" : "=r"(a) : "l"(p));
    return a;
}

#define LDSM_X4(r, addr) \
    asm volatile("ldmatrix.sync.aligned.m8n8.x4.shared.b16 {%0,%1,%2,%3}, [%4];" \
        : "=r"((r)[0]), "=r"((r)[1]), "=r"((r)[2]), "=r"((r)[3]) : "r"(addr))

__device__ __forceinline__ void mma_bf16(float* d, const uint32_t* a, const uint32_t* b) {
    asm volatile("mma.sync.aligned.m16n8k16.row.col.f32.bf16.bf16.f32 "
        "{%0,%1,%2,%3}, {%4,%5,%6,%7}, {%8,%9}, {%0,%1,%2,%3};"
        : "+f"(d[0]), "+f"(d[1]), "+f"(d[2]), "+f"(d[3])
        : "r"(a[0]), "r"(a[1]), "r"(a[2]), "r"(a[3]), "r"(b[0]), "r"(b[1]));
}

__device__ __forceinline__ uint32_t pack_bf16(float lo, float hi) {
    __nv_bfloat162 t = __floats2bfloat162_rn(lo, hi);
    return *(uint32_t*)&t;
}

// ---------------- staging: one plane = input row r_in, 64 ci, 132 cols ----------------
// 40 tasks: oct(8) x colgroup(5); 16 warps -> up to 3 rounds, guarded.
__device__ __forceinline__ void stage_plane_direct(
    const float* __restrict__ x, int n, int r_in, int ow0,
    uint32_t sb, int wid, int lane)
{
    const uint32_t slotB = sb + OFF_S + (uint32_t)(r_in & 3) * S_PLANEB;
    #pragma unroll
    for (int j = 0; j < 3; ++j) {
        int tk = wid + NWARPS * j;
        if (tk >= 40) break;
        int oct = tk / 5;
        int cg  = tk - oct * 5;
        int col = cg * 32 + lane;
        bool stv = (col < 132);
        bool ldv = stv && (ow0 + col < HW);
        const float* gp = x + ((size_t)n * CI + oct * 8) * PLANE
                            + (size_t)r_in * HW + (ow0 + col);
        float v[8];
        #pragma unroll
        for (int q = 0; q < 8; ++q) v[q] = ldv ? gp[(size_t)q * PLANE] : 0.0f;
        if (stv) {
            uint32_t pk0 = pack_bf16(v[0], v[1]);
            uint32_t pk1 = pack_bf16(v[2], v[3]);
            uint32_t pk2 = pack_bf16(v[4], v[5]);
            uint32_t pk3 = pack_bf16(v[6], v[7]);
            uint32_t sa = slotB + (uint32_t)col * S_COLB + (uint32_t)oct * 16;
            asm volatile("st.shared.v4.b32 [%0], {%1,%2,%3,%4};"
                         :: "r"(sa), "r"(pk0), "r"(pk1), "r"(pk2), "r"(pk3));
        }
    }
}

// ---------------- kernel ----------------
__global__ __launch_bounds__(THREADS, 1)
void conv_min_tanh_mma3(const float* __restrict__ x,
                        const float* __restrict__ wgt,
                        const float* __restrict__ bias,
                        float* __restrict__ out)
{
    extern __shared__ char smem[];
    const uint32_t sb = smem_u32(smem);
    const int tid  = threadIdx.x;
    const int lane = tid & 31;
    const int wid  = tid >> 5;
    const int wm   = wid & 3;   // pixel group (32 pixels)
    const int wn   = wid >> 2;  // co quarter (32 co)
    float* bias_sm = (float*)(smem + OFF_BIAS);
    float* min_sm  = (float*)(smem + OFF_MIN);

    // ---- stage weights once: W[co][k], k = kp*64 + ci, bf16 ----
    for (int i = tid; i < CO * KTOT; i += THREADS) {
        int co  = i / KTOT;
        int rem = i - co * KTOT;        // ci*9 + kp
        int ci  = rem / KPOS;
        int kp  = rem - ci * KPOS;
        int k   = kp * 64 + ci;
        *(__nv_bfloat16*)(smem + OFF_W + co * W_ROWB + k * 2) = __float2bfloat16(wgt[i]);
    }
    if (tid < CO) bias_sm[tid] = bias[tid];
    __syncthreads();

    // per-thread bias regs: co = wn*32 + nt*8 + 2*(lane&3) + {0,1}, nt in [0,4)
    float blo[4], bhi[4];
    #pragma unroll
    for (int nt = 0; nt < 4; ++nt) {
        int c = wn * 32 + nt * 8 + 2 * (lane & 3);
        blo[nt] = bias_sm[c];
        bhi[nt] = bias_sm[c + 1];
    }

    // ldmatrix lane address components
    const uint32_t aCol = (uint32_t)(wm * 32 + (lane & 15)) * S_COLB
                        + (uint32_t)(lane >> 4) * 16;
    const uint32_t bBase = sb + OFF_W
        + (uint32_t)(wn * 32 + (lane & 7) + ((lane >> 4) & 1) * 8) * W_ROWB
        + (uint32_t)((lane >> 3) & 1) * 16;

    int prev_strip = -1;

    for (int iter = 0; iter < TILES_PER_CTA; ++iter) {
        const int t     = blockIdx.x * TILES_PER_CTA + iter;
        const int strip = t / OH;              // 0..31 : (n, half)
        const int oh    = t - strip * OH;      // row within strip
        const int n     = strip >> 1;
        const int ow0   = (strip & 1) ? (OW - 128) : 0;

        // ---- strip entry: stage 3 planes fresh ----
        if (strip != prev_strip) {
            stage_plane_direct(x, n, oh + 0, ow0, sb, wid, lane);
            stage_plane_direct(x, n, oh + 1, ow0, sb, wid, lane);
            stage_plane_direct(x, n, oh + 2, ow0, sb, wid, lane);
            __syncthreads();
            prev_strip = strip;
        }

        const bool next_same = (iter + 1 < TILES_PER_CTA) && (oh + 1 < OH);

        // ---- prefetch next plane (input row oh+3) into registers ----
        float pf[3][8];
        if (next_same) {
            const int r_in = oh + 3;
            #pragma unroll
            for (int j = 0; j < 3; ++j) {
                int tk = wid + NWARPS * j;
                if (tk >= 40) break;
                int oct = tk / 5;
                int cg  = tk - oct * 5;
                int col = cg * 32 + lane;
                bool ldv = (col < 132) && (ow0 + col < HW);
                const float* gp = x + ((size_t)n * CI + oct * 8) * PLANE
                                    + (size_t)r_in * HW + (ow0 + col);
                #pragma unroll
                for (int q = 0; q < 8; ++q) pf[j][q] = ldv ? gp[(size_t)q * PLANE] : 0.0f;
            }
        }

        // ---- MMA: K = 9 kpos x 4 ksteps of 16; warp tile 32px x 32co ----
        float acc[2][4][4];
        #pragma unroll
        for (int mi = 0; mi < 2; ++mi)
            #pragma unroll
            for (int nt = 0; nt < 4; ++nt)
                #pragma unroll
                for (int q = 0; q < 4; ++q) acc[mi][nt][q] = 0.0f;

        #pragma unroll 1
        for (int kp = 0; kp < KPOS; ++kp) {
            const int kh = kp / 3, kw = kp - 3 * (kp / 3);
            const uint32_t aKp = sb + OFF_S + (uint32_t)((oh + kh) & 3) * S_PLANEB
                               + aCol + (uint32_t)kw * S_COLB;
            const uint32_t kB  = (uint32_t)(kp * 64) * 2;
            #pragma unroll
            for (int ks = 0; ks < 4; ++ks) {
                uint32_t a0[4], a1[4];
                LDSM_X4(a0, aKp + ks * 32);
                LDSM_X4(a1, aKp + ks * 32 + 16 * S_COLB);
                uint32_t bf[2][4];
                #pragma unroll
                for (int ntp = 0; ntp < 2; ++ntp)
                    LDSM_X4(bf[ntp], bBase + (uint32_t)ntp * 16 * W_ROWB + kB + ks * 32);
                #pragma unroll
                for (int ntp = 0; ntp < 2; ++ntp) {
                    mma_bf16(acc[0][2 * ntp + 0], a0, &bf[ntp][0]);
                    mma_bf16(acc[0][2 * ntp + 1], a0, &bf[ntp][2]);
                    mma_bf16(acc[1][2 * ntp + 0], a1, &bf[ntp][0]);
                    mma_bf16(acc[1][2 * ntp + 1], a1, &bf[ntp][2]);
                }
            }
        }

        // ---- epilogue: bias + min over this warp's 32 co ----
        float v4[4];  // [mi*2 + h], h: 0 = row, 1 = row+8
        #pragma unroll
        for (int mi = 0; mi < 2; ++mi) {
            float r0 = INFINITY, r1 = INFINITY;
            #pragma unroll
            for (int nt = 0; nt < 4; ++nt) {
                r0 = fminf(r0, fminf(acc[mi][nt][0] + blo[nt], acc[mi][nt][1] + bhi[nt]));
                r1 = fminf(r1, fminf(acc[mi][nt][2] + blo[nt], acc[mi][nt][3] + bhi[nt]));
            }
            v4[mi * 2 + 0] = r0;
            v4[mi * 2 + 1] = r1;
        }
        #pragma unroll
        for (int j = 0; j < 4; ++j) {
            v4[j] = fminf(v4[j], __shfl_xor_sync(0xFFFFFFFFu, v4[j], 1));
            v4[j] = fminf(v4[j], __shfl_xor_sync(0xFFFFFFFFu, v4[j], 2));
        }
        if ((lane & 3) == 0) {
            int row = lane >> 2;
            #pragma unroll
            for (int mi = 0; mi < 2; ++mi) {
                int px0 = wm * 32 + mi * 16 + row;
                min_sm[px0 * 4 + wn]       = v4[mi * 2 + 0];
                min_sm[(px0 + 8) * 4 + wn] = v4[mi * 2 + 1];
            }
        }
        __syncthreads();
        if (tid < 128) {
            float4 q = *(const float4*)(min_sm + tid * 4);
            float m = fminf(fminf(q.x, q.y), fminf(q.z, q.w));
            out[((size_t)n * OH + oh) * OW + ow0 + tid] = tanhf(tanhf(m));
        }

        // ---- store prefetched plane into ring slot (oh+3)&3 ----
        if (next_same) {
            const uint32_t slotB = sb + OFF_S + (uint32_t)((oh + 3) & 3) * S_PLANEB;
            #pragma unroll
            for (int j = 0; j < 3; ++j) {
                int tk = wid + NWARPS * j;
                if (tk >= 40) break;
                int oct = tk / 5;
                int cg  = tk - oct * 5;
                int col = cg * 32 + lane;
                if (col < 132) {
                    uint32_t pk0 = pack_bf16(pf[j][0], pf[j][1]);
                    uint32_t pk1 = pack_bf16(pf[j][2], pf[j][3]);
                    uint32_t pk2 = pack_bf16(pf[j][4], pf[j][5]);
                    uint32_t pk3 = pack_bf16(pf[j][6], pf[j][7]);
                    uint32_t sa = slotB + (uint32_t)col * S_COLB + (uint32_t)oct * 16;
                    asm volatile("st.shared.v4.b32 [%0], {%1,%2,%3,%4};"
                                 :: "r"(sa), "r"(pk0), "r"(pk1), "r"(pk2), "r"(pk3));
                }
            }
        }
        __syncthreads();  // plane visible for next row; min_sm safe for reuse
    }
}

extern "C" void kernel_launch(void* const* d_in, const int* in_sizes, int n_in,
                              void* d_out, int out_size)
{
    const float* x    = (const float*)d_in[0];
    const float* wgt  = (const float*)d_in[1];
    const float* bias = (const float*)d_in[2];
    float* out        = (float*)d_out;

    cudaFuncSetAttribute(conv_min_tanh_mma3,
                         cudaFuncAttributeMaxDynamicSharedMemorySize, SMEM_TOTAL);
    conv_min_tanh_mma3<<<NSM, THREADS, SMEM_TOTAL>>>(x, wgt, bias, out);
}